// round 7
// baseline (speedup 1.0000x reference)
#include <cuda_runtime.h>
#include <cuda_fp16.h>
#include <cstdint>

#define BB 8
#define CC 64
#define NN 4096
#define CI 8

// ---------------- scratch (no allocation allowed) ----------------
__device__ __align__(16) __half g_qh[BB * NN * CI];     // [b][n][8]
__device__ __align__(16) __half g_kh[BB * NN * CI];     // [b][m][8], pre-scaled log2e/sqrt(8)
__device__ __align__(16) __half g_vt[BB * CI * NN];     // [b][i][n]  (V transposed)
__device__ __align__(16) float  g_pA[4 * BB * NN * CI]; // [q][b][m][8] partial P@V
__device__ __align__(16) float  g_pD[4 * BB * NN];      // [q][b][m]   partial denom
__device__ int g_cnt[BB * 32];                          // split-K arrival counters (self-reset)

// ---------------- mma helpers (baseline sm_80+ features only) --------------
__device__ __forceinline__ void mma_s_f16(uint32_t& d0, uint32_t& d1,
                                          uint32_t a0, uint32_t a1, uint32_t b0) {
    asm("mma.sync.aligned.m16n8k8.row.col.f16.f16.f16.f16 "
        "{%0,%1}, {%2,%3}, {%4}, {%5,%6};"
        : "=r"(d0), "=r"(d1)
        : "r"(a0), "r"(a1), "r"(b0), "r"(0u), "r"(0u));
}
__device__ __forceinline__ void mma_pv_f16(uint32_t& c0, uint32_t& c1,
                                           uint32_t a0, uint32_t a1, uint32_t a2, uint32_t a3,
                                           uint32_t b0, uint32_t b1) {
    asm("mma.sync.aligned.m16n8k16.row.col.f16.f16.f16.f16 "
        "{%0,%1}, {%2,%3,%4,%5}, {%6,%7}, {%0,%1};"
        : "+r"(c0), "+r"(c1)
        : "r"(a0), "r"(a1), "r"(a2), "r"(a3), "r"(b0), "r"(b1));
}
__device__ __forceinline__ void mma_m16n8k16_f32(float& c0, float& c1, float& c2, float& c3,
                                                 uint32_t a0, uint32_t a1, uint32_t a2, uint32_t a3,
                                                 uint32_t b0, uint32_t b1) {
    asm("mma.sync.aligned.m16n8k16.row.col.f32.f16.f16.f32 "
        "{%0,%1,%2,%3}, {%4,%5,%6,%7}, {%8,%9}, {%0,%1,%2,%3};"
        : "+f"(c0), "+f"(c1), "+f"(c2), "+f"(c3)
        : "r"(a0), "r"(a1), "r"(a2), "r"(a3), "r"(b0), "r"(b1));
}
__device__ __forceinline__ uint32_t ex2_h2(uint32_t x) {
    uint32_t r;
    asm("ex2.approx.f16x2 %0, %1;" : "=r"(r) : "r"(x));
    return r;
}
__device__ __forceinline__ uint32_t hadd2u(uint32_t a, uint32_t b) {
    __half2 r = __hadd2(*reinterpret_cast<__half2*>(&a), *reinterpret_cast<__half2*>(&b));
    return *reinterpret_cast<uint32_t*>(&r);
}
__device__ __forceinline__ float2 h2f2(uint32_t a) {
    return __half22float2(*reinterpret_cast<__half2*>(&a));
}
// degree-4 polynomial 2^x on the fma pipe (HFMA2), x in ~[-1.5, 1.5]
__device__ __forceinline__ uint32_t exp2_poly(uint32_t xu, __half2 c4, __half2 c3,
                                              __half2 c2, __half2 c1, __half2 c0) {
    __half2 x = *reinterpret_cast<__half2*>(&xu);
    __half2 p = __hfma2(c4, x, c3);
    p = __hfma2(p, x, c2);
    p = __hfma2(p, x, c1);
    p = __hfma2(p, x, c0);
    return *reinterpret_cast<uint32_t*>(&p);
}

// ---------------- kernel 1: q/k/v projections (4-way c-split) --------------
__global__ void __launch_bounds__(256) proj_kernel(const float* __restrict__ x,
                                                   const float* __restrict__ Wq,
                                                   const float* __restrict__ Wk,
                                                   const float* __restrict__ Wv) {
    __shared__ float swq[CI * CC], swk[CI * CC], swv[CI * CC];
    __shared__ __half sv[CI][64];
    int tid = threadIdx.x;
    for (int i = tid; i < CI * CC; i += 256) {
        swq[i] = Wq[i]; swk[i] = Wk[i]; swv[i] = Wv[i];
    }
    __syncthreads();

    int wid = tid >> 5, lane = tid & 31;
    int quarter = lane >> 3, nl = lane & 7;
    int slot = blockIdx.x * 64 + wid * 8 + nl;     // grid 512 -> 32768 slots
    int b = slot >> 12, n = slot & (NN - 1);
    int nloc = (wid << 3) | nl;

    float q[CI], k[CI], v[CI];
#pragma unroll
    for (int i = 0; i < CI; i++) { q[i] = 0.f; k[i] = 0.f; v[i] = 0.f; }

    const float* xp = x + (size_t)b * CC * NN + n;
    int c0 = quarter * 16;
#pragma unroll
    for (int j = 0; j < 16; j++) {
        int c = c0 + j;
        float xv = xp[(size_t)c * NN];
#pragma unroll
        for (int i = 0; i < CI; i++) {
            q[i] = fmaf(swq[i * CC + c], xv, q[i]);
            k[i] = fmaf(swk[i * CC + c], xv, k[i]);
            v[i] = fmaf(swv[i * CC + c], xv, v[i]);
        }
    }
#pragma unroll
    for (int i = 0; i < CI; i++) {
        q[i] += __shfl_xor_sync(0xffffffffu, q[i], 8);
        k[i] += __shfl_xor_sync(0xffffffffu, k[i], 8);
        v[i] += __shfl_xor_sync(0xffffffffu, v[i], 8);
        q[i] += __shfl_xor_sync(0xffffffffu, q[i], 16);
        k[i] += __shfl_xor_sync(0xffffffffu, k[i], 16);
        v[i] += __shfl_xor_sync(0xffffffffu, v[i], 16);
    }
    if (quarter == 0) {
        const float KS = 0.51006971f;  // log2(e)/sqrt(8)
        size_t base = ((size_t)b * NN + n) * CI;
        __half2 qh[4], kh[4];
#pragma unroll
        for (int i = 0; i < 4; i++) {
            qh[i] = __floats2half2_rn(q[2 * i], q[2 * i + 1]);
            kh[i] = __floats2half2_rn(k[2 * i] * KS, k[2 * i + 1] * KS);
        }
        *reinterpret_cast<uint4*>(&g_qh[base]) = *reinterpret_cast<uint4*>(qh);
        *reinterpret_cast<uint4*>(&g_kh[base]) = *reinterpret_cast<uint4*>(kh);
#pragma unroll
        for (int i = 0; i < CI; i++) sv[i][nloc] = __float2half_rn(v[i]);
    }
    __syncthreads();
    if (tid < 64) {
        int row = tid >> 3, chunk = tid & 7;
        int nbase = (blockIdx.x & 63) * 64;
        int bb = blockIdx.x >> 6;
        *reinterpret_cast<uint4*>(g_vt + ((size_t)bb * CI + row) * NN + nbase + chunk * 8) =
            *reinterpret_cast<const uint4*>(&sv[row][chunk * 8]);
    }
}

// ---------------- kernel 2: FA2 attention, 256-thr CTA + hybrid exp --------
// grid 1024: b = bx>>7, mt = (bx>>2)&31 (128 m each), quarter = bx&3.
// 8 warps: warp w owns m rows [mt*128+16w, +16). n range = quarter*1024.
#define VPAD 264

__global__ void __launch_bounds__(256) attn_kernel(const float* __restrict__ x,
                                                   const float* __restrict__ Wout,
                                                   float* __restrict__ out) {
    __shared__ __align__(16) uint4 sQ[256];          // Q tile [256][8] halves
    __shared__ __align__(16) __half sV[CI * VPAD];   // Vt tile [8][256] padded
    __shared__ float sAtt[128 * 9];
    __shared__ float sW[CC * CI];
    __shared__ int s_old;

    int tid = threadIdx.x, wid = tid >> 5, lane = tid & 31;
    int gid = lane >> 2, cp = lane & 3;
    int b = blockIdx.x >> 7, mt = (blockIdx.x >> 2) & 31, quarter = blockIdx.x & 3;
    int m0 = mt * 128;
    int nbase = quarter * 1024;

    int mrow = m0 + wid * 16 + gid;
    uint32_t ka0 = *reinterpret_cast<const uint32_t*>(
        &g_kh[((size_t)b * NN + mrow) * CI + 2 * cp]);
    uint32_t ka1 = *reinterpret_cast<const uint32_t*>(
        &g_kh[((size_t)b * NN + mrow + 8) * CI + 2 * cp]);

    const uint4* qbase = reinterpret_cast<const uint4*>(g_qh + (size_t)b * NN * CI);
    const __half* vbase = g_vt + (size_t)b * CI * NN;

    // polynomial coefficients for 2^x (Taylor in ln2, deg 4)
    const __half2 c0h = __floats2half2_rn(1.0f, 1.0f);
    const __half2 c1h = __floats2half2_rn(0.6931472f, 0.6931472f);
    const __half2 c2h = __floats2half2_rn(0.2402265f, 0.2402265f);
    const __half2 c3h = __floats2half2_rn(0.0555041f, 0.0555041f);
    const __half2 c4h = __floats2half2_rn(0.0096181f, 0.0096181f);

    uint32_t aE0 = 0, aE1 = 0, aO0 = 0, aO1 = 0;
    float den0 = 0.f, den1 = 0.f, den2 = 0.f, den3 = 0.f;
    const uint32_t ONES = 0x3C003C00u;

    int vr = tid >> 5;              // V row for this thread's tile loads (== wid)
    int vc = (tid & 31) * 8;        // V col (halves)

    uint4 q4 = qbase[nbase + tid];
    uint4 v4 = *reinterpret_cast<const uint4*>(vbase + (size_t)vr * NN + nbase + vc);

    const uint32_t* sQw = reinterpret_cast<const uint32_t*>(sQ);
    const uint32_t* qp = sQw + gid * 4 + cp;
    const __half* vp = sV + gid * VPAD + 2 * cp;

    for (int bi = 0; bi < 4; bi++) {
        sQ[tid] = q4;
        *reinterpret_cast<uint4*>(&sV[vr * VPAD + vc]) = v4;
        __syncthreads();

        if (bi < 3) {
            int n1 = nbase + (bi + 1) * 256;
            q4 = qbase[n1 + tid];
            v4 = *reinterpret_cast<const uint4*>(vbase + (size_t)vr * NN + n1 + vc);
        }

#pragma unroll
        for (int g = 0; g < 4; g++) {
            int no = g * 64;
            uint32_t P[4][4];
#pragma unroll
            for (int c = 0; c < 4; c++) {
                int nc = no + c * 16;
                uint32_t qL = qp[nc * 4];
                uint32_t qH = qp[(nc + 8) * 4];
                uint32_t s01, s23, s45, s67;
                mma_s_f16(s01, s23, ka0, ka1, qL);
                mma_s_f16(s45, s67, ka0, ka1, qH);
                if (c & 1) {   // odd chunks: polynomial exp on fma pipe
                    P[c][0] = exp2_poly(s01, c4h, c3h, c2h, c1h, c0h);
                    P[c][1] = exp2_poly(s23, c4h, c3h, c2h, c1h, c0h);
                    P[c][2] = exp2_poly(s45, c4h, c3h, c2h, c1h, c0h);
                    P[c][3] = exp2_poly(s67, c4h, c3h, c2h, c1h, c0h);
                } else {       // even chunks: MUFU
                    P[c][0] = ex2_h2(s01);
                    P[c][1] = ex2_h2(s23);
                    P[c][2] = ex2_h2(s45);
                    P[c][3] = ex2_h2(s67);
                }
            }
#pragma unroll
            for (int c = 0; c < 4; c++) {
                int nc = no + c * 16;
                uint32_t vb0 = *reinterpret_cast<const uint32_t*>(vp + nc);
                uint32_t vb1 = *reinterpret_cast<const uint32_t*>(vp + nc + 8);
                if (c & 1)
                    mma_pv_f16(aO0, aO1, P[c][0], P[c][1], P[c][2], P[c][3], vb0, vb1);
                else
                    mma_pv_f16(aE0, aE1, P[c][0], P[c][1], P[c][2], P[c][3], vb0, vb1);
            }
            uint32_t t0 = hadd2u(hadd2u(P[0][0], P[1][0]), hadd2u(P[2][0], P[3][0]));
            uint32_t t1 = hadd2u(hadd2u(P[0][1], P[1][1]), hadd2u(P[2][1], P[3][1]));
            uint32_t t2 = hadd2u(hadd2u(P[0][2], P[1][2]), hadd2u(P[2][2], P[3][2]));
            uint32_t t3 = hadd2u(hadd2u(P[0][3], P[1][3]), hadd2u(P[2][3], P[3][3]));
            mma_m16n8k16_f32(den0, den1, den2, den3, t0, t1, t2, t3, ONES, ONES);
        }
        __syncthreads();
    }

    float2 e0 = h2f2(aE0), e1 = h2f2(aE1), o0 = h2f2(aO0), o1 = h2f2(aO1);
    float acc0 = e0.x + o0.x, acc1 = e0.y + o0.y;
    float acc2 = e1.x + o1.x, acc3 = e1.y + o1.y;

    {
        size_t rb = ((size_t)quarter * BB + b) * NN;
        *reinterpret_cast<float2*>(&g_pA[(rb + mrow) * CI + 2 * cp]) = make_float2(acc0, acc1);
        *reinterpret_cast<float2*>(&g_pA[(rb + mrow + 8) * CI + 2 * cp]) = make_float2(acc2, acc3);
        if (cp == 0) {
            g_pD[rb + mrow] = den0;
            g_pD[rb + mrow + 8] = den2;
        }
    }
    __threadfence();
    __syncthreads();
    if (tid == 0) s_old = atomicAdd(&g_cnt[b * 32 + mt], 1);
    __syncthreads();
    if (s_old != 3) return;                // first three exit; last merges + epilogue
    if (tid == 0) g_cnt[b * 32 + mt] = 0;  // reset for next (graph-replayed) launch
    __threadfence();

    for (int i = tid; i < CC * CI; i += 256) sW[i] = Wout[i];
    if (tid < 128) {
        int m = m0 + tid;
        float acc[CI] = {0, 0, 0, 0, 0, 0, 0, 0};
        float den = 0.f;
#pragma unroll
        for (int qq = 0; qq < 4; qq++) {
            size_t rb = ((size_t)qq * BB + b) * NN + m;
            const float4* a = reinterpret_cast<const float4*>(&g_pA[rb * CI]);
            float4 x0 = a[0], x1 = a[1];
            acc[0] += x0.x; acc[1] += x0.y; acc[2] += x0.z; acc[3] += x0.w;
            acc[4] += x1.x; acc[5] += x1.y; acc[6] += x1.z; acc[7] += x1.w;
            den += g_pD[rb];
        }
        float inv = 1.0f / den;
#pragma unroll
        for (int i = 0; i < CI; i++) sAtt[tid * 9 + i] = acc[i] * inv;
    }
    __syncthreads();

    // epilogue: out = x + 0.1 * Wout @ att (256 threads: 128 m x 2 c-halves)
    int ml = tid & 127, chalf = tid >> 7;
    float att[CI];
#pragma unroll
    for (int i = 0; i < CI; i++) att[i] = sAtt[ml * 9 + i];

    int m = m0 + ml;
    const float* xp = x + (size_t)b * CC * NN + m;
    float* op = out + (size_t)b * CC * NN + m;
#pragma unroll 8
    for (int j = 0; j < 32; j++) {
        int c = chalf * 32 + j;
        float o = 0.f;
#pragma unroll
        for (int i = 0; i < CI; i++) o = fmaf(sW[c * CI + i], att[i], o);
        op[(size_t)c * NN] = fmaf(0.1f, o, xp[(size_t)c * NN]);
    }
}

// ---------------- launch ----------------
extern "C" void kernel_launch(void* const* d_in, const int* in_sizes, int n_in,
                              void* d_out, int out_size) {
    const float* x = (const float*)d_in[0];
    const float* Wq = (const float*)d_in[1];
    const float* Wk = (const float*)d_in[2];
    const float* Wv = (const float*)d_in[3];
    const float* Wout = (const float*)d_in[4];
    float* out = (float*)d_out;

    proj_kernel<<<512, 256>>>(x, Wq, Wk, Wv);
    attn_kernel<<<1024, 256>>>(x, Wout, out);
}

// round 8
// speedup vs baseline: 1.0535x; 1.0535x over previous
#include <cuda_runtime.h>
#include <cuda_fp16.h>
#include <cstdint>

#define BB 8
#define CC 64
#define NN 4096
#define CI 8
#define SPLITK 8

// ---------------- scratch (no allocation allowed) ----------------
__device__ __align__(16) __half g_qh[BB * NN * CI];          // [b][n][8]
__device__ __align__(16) __half g_kh[BB * NN * CI];          // [b][m][8], pre-scaled log2e/sqrt(8)
__device__ __align__(16) __half g_vt[BB * CI * NN];          // [b][i][n]  (V transposed)
__device__ __align__(16) float  g_pA[SPLITK * BB * NN * CI]; // [s][b][m][8] partial P@V
__device__ __align__(16) float  g_pD[SPLITK * BB * NN];      // [s][b][m]   partial denom
__device__ int g_cnt[BB * 64];                               // split-K counters (self-reset)

// ---------------- mma helpers (baseline sm_80+ features only) --------------
__device__ __forceinline__ void mma_s_f16(uint32_t& d0, uint32_t& d1,
                                          uint32_t a0, uint32_t a1, uint32_t b0) {
    asm("mma.sync.aligned.m16n8k8.row.col.f16.f16.f16.f16 "
        "{%0,%1}, {%2,%3}, {%4}, {%5,%6};"
        : "=r"(d0), "=r"(d1)
        : "r"(a0), "r"(a1), "r"(b0), "r"(0u), "r"(0u));
}
__device__ __forceinline__ void mma_pv_f16(uint32_t& c0, uint32_t& c1,
                                           uint32_t a0, uint32_t a1, uint32_t a2, uint32_t a3,
                                           uint32_t b0, uint32_t b1) {
    asm("mma.sync.aligned.m16n8k16.row.col.f16.f16.f16.f16 "
        "{%0,%1}, {%2,%3,%4,%5}, {%6,%7}, {%0,%1};"
        : "+r"(c0), "+r"(c1)
        : "r"(a0), "r"(a1), "r"(a2), "r"(a3), "r"(b0), "r"(b1));
}
__device__ __forceinline__ void mma_m16n8k16_f32(float& c0, float& c1, float& c2, float& c3,
                                                 uint32_t a0, uint32_t a1, uint32_t a2, uint32_t a3,
                                                 uint32_t b0, uint32_t b1) {
    asm("mma.sync.aligned.m16n8k16.row.col.f32.f16.f16.f32 "
        "{%0,%1,%2,%3}, {%4,%5,%6,%7}, {%8,%9}, {%0,%1,%2,%3};"
        : "+f"(c0), "+f"(c1), "+f"(c2), "+f"(c3)
        : "r"(a0), "r"(a1), "r"(a2), "r"(a3), "r"(b0), "r"(b1));
}
__device__ __forceinline__ uint32_t ex2_h2(uint32_t x) {
    uint32_t r;
    asm("ex2.approx.f16x2 %0, %1;" : "=r"(r) : "r"(x));
    return r;
}
__device__ __forceinline__ uint32_t hadd2u(uint32_t a, uint32_t b) {
    __half2 r = __hadd2(*reinterpret_cast<__half2*>(&a), *reinterpret_cast<__half2*>(&b));
    return *reinterpret_cast<uint32_t*>(&r);
}
__device__ __forceinline__ float2 h2f2(uint32_t a) {
    return __half22float2(*reinterpret_cast<__half2*>(&a));
}
// degree-4 polynomial 2^x on the fma pipe (HFMA2), x in ~[-1.5, 1.5]
__device__ __forceinline__ uint32_t exp2_poly(uint32_t xu) {
    const __half2 c4 = __floats2half2_rn(0.0096181f, 0.0096181f);
    const __half2 c3 = __floats2half2_rn(0.0555041f, 0.0555041f);
    const __half2 c2 = __floats2half2_rn(0.2402265f, 0.2402265f);
    const __half2 c1 = __floats2half2_rn(0.6931472f, 0.6931472f);
    const __half2 c0 = __floats2half2_rn(1.0f, 1.0f);
    __half2 x = *reinterpret_cast<__half2*>(&xu);
    __half2 p = __hfma2(c4, x, c3);
    p = __hfma2(p, x, c2);
    p = __hfma2(p, x, c1);
    p = __hfma2(p, x, c0);
    return *reinterpret_cast<uint32_t*>(&p);
}

// ---------------- kernel 1: q/k/v projections (4-way c-split) --------------
__global__ void __launch_bounds__(256) proj_kernel(const float* __restrict__ x,
                                                   const float* __restrict__ Wq,
                                                   const float* __restrict__ Wk,
                                                   const float* __restrict__ Wv) {
    __shared__ float swq[CI * CC], swk[CI * CC], swv[CI * CC];
    __shared__ __half sv[CI][64];
    int tid = threadIdx.x;
    for (int i = tid; i < CI * CC; i += 256) {
        swq[i] = Wq[i]; swk[i] = Wk[i]; swv[i] = Wv[i];
    }
    __syncthreads();

    int wid = tid >> 5, lane = tid & 31;
    int quarter = lane >> 3, nl = lane & 7;
    int slot = blockIdx.x * 64 + wid * 8 + nl;     // grid 512 -> 32768 slots
    int b = slot >> 12, n = slot & (NN - 1);
    int nloc = (wid << 3) | nl;

    float q[CI], k[CI], v[CI];
#pragma unroll
    for (int i = 0; i < CI; i++) { q[i] = 0.f; k[i] = 0.f; v[i] = 0.f; }

    const float* xp = x + (size_t)b * CC * NN + n;
    int c0 = quarter * 16;
#pragma unroll
    for (int j = 0; j < 16; j++) {
        int c = c0 + j;
        float xv = xp[(size_t)c * NN];
#pragma unroll
        for (int i = 0; i < CI; i++) {
            q[i] = fmaf(swq[i * CC + c], xv, q[i]);
            k[i] = fmaf(swk[i * CC + c], xv, k[i]);
            v[i] = fmaf(swv[i * CC + c], xv, v[i]);
        }
    }
#pragma unroll
    for (int i = 0; i < CI; i++) {
        q[i] += __shfl_xor_sync(0xffffffffu, q[i], 8);
        k[i] += __shfl_xor_sync(0xffffffffu, k[i], 8);
        v[i] += __shfl_xor_sync(0xffffffffu, v[i], 8);
        q[i] += __shfl_xor_sync(0xffffffffu, q[i], 16);
        k[i] += __shfl_xor_sync(0xffffffffu, k[i], 16);
        v[i] += __shfl_xor_sync(0xffffffffu, v[i], 16);
    }
    if (quarter == 0) {
        const float KS = 0.51006971f;  // log2(e)/sqrt(8)
        size_t base = ((size_t)b * NN + n) * CI;
        __half2 qh[4], kh[4];
#pragma unroll
        for (int i = 0; i < 4; i++) {
            qh[i] = __floats2half2_rn(q[2 * i], q[2 * i + 1]);
            kh[i] = __floats2half2_rn(k[2 * i] * KS, k[2 * i + 1] * KS);
        }
        *reinterpret_cast<uint4*>(&g_qh[base]) = *reinterpret_cast<uint4*>(qh);
        *reinterpret_cast<uint4*>(&g_kh[base]) = *reinterpret_cast<uint4*>(kh);
#pragma unroll
        for (int i = 0; i < CI; i++) sv[i][nloc] = __float2half_rn(v[i]);
    }
    __syncthreads();
    if (tid < 64) {
        int row = tid >> 3, chunk = tid & 7;
        int nbase = (blockIdx.x & 63) * 64;
        int bb = blockIdx.x >> 6;
        *reinterpret_cast<uint4*>(g_vt + ((size_t)bb * CI + row) * NN + nbase + chunk * 8) =
            *reinterpret_cast<const uint4*>(&sv[row][chunk * 8]);
    }
}

// ---------------- kernel 2: FA2 attention, split-K(8) + hybrid exp ---------
// grid 4096: b = bx>>9, mt = (bx>>3)&63 (64 m rows), s8 = bx&7 (512 n each).
// 128 threads = 4 warps; warp w owns m rows [m0+16w, m0+16w+16).
#define VPAD 264

__global__ void __launch_bounds__(128, 8) attn_kernel(const float* __restrict__ x,
                                                      const float* __restrict__ Wout,
                                                      float* __restrict__ out) {
    __shared__ __align__(16) uint4 sQ[256];          // Q tile [256][8] halves
    __shared__ __align__(16) __half sV[CI * VPAD];   // Vt tile [8][256] padded
    __shared__ float sAtt[64 * 9];
    __shared__ float sW[CC * CI];
    __shared__ int s_old;

    int tid = threadIdx.x, wid = tid >> 5, lane = tid & 31;
    int gid = lane >> 2, cp = lane & 3;
    int b = blockIdx.x >> 9, mt = (blockIdx.x >> 3) & 63, s8 = blockIdx.x & 7;
    int m0 = mt * 64;
    int nbase = s8 * 512;

    int mrow = m0 + wid * 16 + gid;
    uint32_t ka0 = *reinterpret_cast<const uint32_t*>(
        &g_kh[((size_t)b * NN + mrow) * CI + 2 * cp]);
    uint32_t ka1 = *reinterpret_cast<const uint32_t*>(
        &g_kh[((size_t)b * NN + mrow + 8) * CI + 2 * cp]);

    const uint4* qbase = reinterpret_cast<const uint4*>(g_qh + (size_t)b * NN * CI);
    const __half* vbase = g_vt + (size_t)b * CI * NN;

    uint32_t aE0 = 0, aE1 = 0, aO0 = 0, aO1 = 0;
    float den0 = 0.f, den1 = 0.f, den2 = 0.f, den3 = 0.f;
    const uint32_t ONES = 0x3C003C00u;

    int r0 = tid >> 5, c0i = tid & 31;
    int r1 = (tid + 128) >> 5;

    uint4 q4a = qbase[nbase + tid];
    uint4 q4b = qbase[nbase + tid + 128];
    uint4 v4a = *reinterpret_cast<const uint4*>(vbase + (size_t)r0 * NN + nbase + c0i * 8);
    uint4 v4b = *reinterpret_cast<const uint4*>(vbase + (size_t)r1 * NN + nbase + c0i * 8);

    const uint32_t* sQw = reinterpret_cast<const uint32_t*>(sQ);
    const uint32_t* qp = sQw + gid * 4 + cp;
    const __half* vp = sV + gid * VPAD + 2 * cp;

    for (int bi = 0; bi < 2; bi++) {
        sQ[tid] = q4a;
        sQ[tid + 128] = q4b;
        *reinterpret_cast<uint4*>(&sV[r0 * VPAD + c0i * 8]) = v4a;
        *reinterpret_cast<uint4*>(&sV[r1 * VPAD + c0i * 8]) = v4b;
        __syncthreads();

        if (bi < 1) {
            int n1 = nbase + 256;
            q4a = qbase[n1 + tid];
            q4b = qbase[n1 + tid + 128];
            v4a = *reinterpret_cast<const uint4*>(vbase + (size_t)r0 * NN + n1 + c0i * 8);
            v4b = *reinterpret_cast<const uint4*>(vbase + (size_t)r1 * NN + n1 + c0i * 8);
        }

#pragma unroll
        for (int g = 0; g < 4; g++) {
            int no = g * 64;
            uint32_t P[4][4];
#pragma unroll
            for (int c = 0; c < 4; c++) {
                int nc = no + c * 16;
                uint32_t qL = qp[nc * 4];
                uint32_t qH = qp[(nc + 8) * 4];
                uint32_t s01, s23, s45, s67;
                mma_s_f16(s01, s23, ka0, ka1, qL);
                mma_s_f16(s45, s67, ka0, ka1, qH);
                if (c & 1) {   // odd chunks: polynomial exp on fma pipe
                    P[c][0] = exp2_poly(s01);
                    P[c][1] = exp2_poly(s23);
                    P[c][2] = exp2_poly(s45);
                    P[c][3] = exp2_poly(s67);
                } else {       // even chunks: MUFU
                    P[c][0] = ex2_h2(s01);
                    P[c][1] = ex2_h2(s23);
                    P[c][2] = ex2_h2(s45);
                    P[c][3] = ex2_h2(s67);
                }
            }
#pragma unroll
            for (int c = 0; c < 4; c++) {
                int nc = no + c * 16;
                uint32_t vb0 = *reinterpret_cast<const uint32_t*>(vp + nc);
                uint32_t vb1 = *reinterpret_cast<const uint32_t*>(vp + nc + 8);
                if (c & 1)
                    mma_pv_f16(aO0, aO1, P[c][0], P[c][1], P[c][2], P[c][3], vb0, vb1);
                else
                    mma_pv_f16(aE0, aE1, P[c][0], P[c][1], P[c][2], P[c][3], vb0, vb1);
            }
            uint32_t t0 = hadd2u(hadd2u(P[0][0], P[1][0]), hadd2u(P[2][0], P[3][0]));
            uint32_t t1 = hadd2u(hadd2u(P[0][1], P[1][1]), hadd2u(P[2][1], P[3][1]));
            uint32_t t2 = hadd2u(hadd2u(P[0][2], P[1][2]), hadd2u(P[2][2], P[3][2]));
            uint32_t t3 = hadd2u(hadd2u(P[0][3], P[1][3]), hadd2u(P[2][3], P[3][3]));
            mma_m16n8k16_f32(den0, den1, den2, den3, t0, t1, t2, t3, ONES, ONES);
        }
        __syncthreads();
    }

    float2 e0 = h2f2(aE0), e1 = h2f2(aE1), o0 = h2f2(aO0), o1 = h2f2(aO1);
    float acc0 = e0.x + o0.x, acc1 = e0.y + o0.y;
    float acc2 = e1.x + o1.x, acc3 = e1.y + o1.y;

    {
        size_t rb = ((size_t)s8 * BB + b) * NN;
        *reinterpret_cast<float2*>(&g_pA[(rb + mrow) * CI + 2 * cp]) = make_float2(acc0, acc1);
        *reinterpret_cast<float2*>(&g_pA[(rb + mrow + 8) * CI + 2 * cp]) = make_float2(acc2, acc3);
        if (cp == 0) {
            g_pD[rb + mrow] = den0;
            g_pD[rb + mrow + 8] = den2;
        }
    }
    __threadfence();
    __syncthreads();
    if (tid == 0) s_old = atomicAdd(&g_cnt[b * 64 + mt], 1);
    __syncthreads();
    if (s_old != SPLITK - 1) return;       // last-arriving CTA merges + epilogue
    if (tid == 0) g_cnt[b * 64 + mt] = 0;  // reset for next (graph-replayed) launch
    __threadfence();

    for (int i = tid; i < CC * CI; i += 128) sW[i] = Wout[i];
    if (tid < 64) {
        int m = m0 + tid;
        float acc[CI] = {0, 0, 0, 0, 0, 0, 0, 0};
        float den = 0.f;
#pragma unroll
        for (int qq = 0; qq < SPLITK; qq++) {
            size_t rb = ((size_t)qq * BB + b) * NN + m;
            const float4* a = reinterpret_cast<const float4*>(&g_pA[rb * CI]);
            float4 x0 = a[0], x1 = a[1];
            acc[0] += x0.x; acc[1] += x0.y; acc[2] += x0.z; acc[3] += x0.w;
            acc[4] += x1.x; acc[5] += x1.y; acc[6] += x1.z; acc[7] += x1.w;
            den += g_pD[rb];
        }
        float inv = 1.0f / den;
#pragma unroll
        for (int i = 0; i < CI; i++) sAtt[tid * 9 + i] = acc[i] * inv;
    }
    __syncthreads();

    // epilogue: out = x + 0.1 * Wout @ att
    int ml = tid & 63, chalf = tid >> 6;
    float att[CI];
#pragma unroll
    for (int i = 0; i < CI; i++) att[i] = sAtt[ml * 9 + i];

    int m = m0 + ml;
    const float* xp = x + (size_t)b * CC * NN + m;
    float* op = out + (size_t)b * CC * NN + m;
#pragma unroll 8
    for (int j = 0; j < 32; j++) {
        int c = chalf * 32 + j;
        float o = 0.f;
#pragma unroll
        for (int i = 0; i < CI; i++) o = fmaf(sW[c * CI + i], att[i], o);
        op[(size_t)c * NN] = fmaf(0.1f, o, xp[(size_t)c * NN]);
    }
}

// ---------------- launch ----------------
extern "C" void kernel_launch(void* const* d_in, const int* in_sizes, int n_in,
                              void* d_out, int out_size) {
    const float* x = (const float*)d_in[0];
    const float* Wq = (const float*)d_in[1];
    const float* Wk = (const float*)d_in[2];
    const float* Wv = (const float*)d_in[3];
    const float* Wout = (const float*)d_in[4];
    float* out = (float*)d_out;

    proj_kernel<<<512, 256>>>(x, Wq, Wk, Wv);
    attn_kernel<<<4096, 128>>>(x, Wout, out);
}

// round 9
// speedup vs baseline: 1.0673x; 1.0131x over previous
#include <cuda_runtime.h>
#include <cuda_fp16.h>
#include <cstdint>

#define BB 8
#define CC 64
#define NN 4096
#define CI 8
#define SPLITK 8

// ---------------- scratch (no allocation allowed) ----------------
__device__ __align__(16) __half g_qh[BB * NN * CI];          // [b][n][8]
__device__ __align__(16) __half g_kh[BB * NN * CI];          // [b][m][8], pre-scaled log2e/sqrt(8)
__device__ __align__(16) __half g_vt[BB * CI * NN];          // [b][i][n]  (V transposed)
__device__ __align__(16) float  g_pA[SPLITK * BB * NN * CI]; // [s][b][m][8] partial P@V
__device__ __align__(16) float  g_pD[SPLITK * BB * NN];      // [s][b][m]   partial denom
__device__ int g_cnt[BB * 32];                               // split-K counters (self-reset)

// ---------------- mma helpers (baseline sm_80+ features only) --------------
__device__ __forceinline__ void mma_s_f16(uint32_t& d0, uint32_t& d1,
                                          uint32_t a0, uint32_t a1, uint32_t b0) {
    asm("mma.sync.aligned.m16n8k8.row.col.f16.f16.f16.f16 "
        "{%0,%1}, {%2,%3}, {%4}, {%5,%6};"
        : "=r"(d0), "=r"(d1)
        : "r"(a0), "r"(a1), "r"(b0), "r"(0u), "r"(0u));
}
__device__ __forceinline__ void mma_pv_f16(uint32_t& c0, uint32_t& c1,
                                           uint32_t a0, uint32_t a1, uint32_t a2, uint32_t a3,
                                           uint32_t b0, uint32_t b1) {
    asm("mma.sync.aligned.m16n8k16.row.col.f16.f16.f16.f16 "
        "{%0,%1}, {%2,%3,%4,%5}, {%6,%7}, {%0,%1};"
        : "+r"(c0), "+r"(c1)
        : "r"(a0), "r"(a1), "r"(a2), "r"(a3), "r"(b0), "r"(b1));
}
__device__ __forceinline__ uint32_t ex2_h2(uint32_t x) {
    uint32_t r;
    asm("ex2.approx.f16x2 %0, %1;" : "=r"(r) : "r"(x));
    return r;
}
__device__ __forceinline__ uint32_t hadd2u(uint32_t a, uint32_t b) {
    __half2 r = __hadd2(*reinterpret_cast<__half2*>(&a), *reinterpret_cast<__half2*>(&b));
    return *reinterpret_cast<uint32_t*>(&r);
}
__device__ __forceinline__ float2 h2f2(uint32_t a) {
    return __half22float2(*reinterpret_cast<__half2*>(&a));
}
// degree-3 polynomial 2^x on the fma pipe (3 HFMA2), x in ~[-1.5, 1.5]
__device__ __forceinline__ uint32_t exp2_poly3(uint32_t xu) {
    const __half2 c3 = __floats2half2_rn(0.0558f, 0.0558f);
    const __half2 c2 = __floats2half2_rn(0.2402f, 0.2402f);
    const __half2 c1 = __floats2half2_rn(0.6932f, 0.6932f);
    const __half2 c0 = __floats2half2_rn(1.0f, 1.0f);
    __half2 x = *reinterpret_cast<__half2*>(&xu);
    __half2 p = __hfma2(c3, x, c2);
    p = __hfma2(p, x, c1);
    p = __hfma2(p, x, c0);
    return *reinterpret_cast<uint32_t*>(&p);
}

// ---------------- kernel 1: q/k/v projections (4-way c-split) --------------
__global__ void __launch_bounds__(256) proj_kernel(const float* __restrict__ x,
                                                   const float* __restrict__ Wq,
                                                   const float* __restrict__ Wk,
                                                   const float* __restrict__ Wv) {
    __shared__ float swq[CI * CC], swk[CI * CC], swv[CI * CC];
    __shared__ __half sv[CI][64];
    int tid = threadIdx.x;
    for (int i = tid; i < CI * CC; i += 256) {
        swq[i] = Wq[i]; swk[i] = Wk[i]; swv[i] = Wv[i];
    }
    __syncthreads();

    int wid = tid >> 5, lane = tid & 31;
    int quarter = lane >> 3, nl = lane & 7;
    int slot = blockIdx.x * 64 + wid * 8 + nl;     // grid 512 -> 32768 slots
    int b = slot >> 12, n = slot & (NN - 1);
    int nloc = (wid << 3) | nl;

    float q[CI], k[CI], v[CI];
#pragma unroll
    for (int i = 0; i < CI; i++) { q[i] = 0.f; k[i] = 0.f; v[i] = 0.f; }

    const float* xp = x + (size_t)b * CC * NN + n;
    int c0 = quarter * 16;
#pragma unroll
    for (int j = 0; j < 16; j++) {
        int c = c0 + j;
        float xv = xp[(size_t)c * NN];
#pragma unroll
        for (int i = 0; i < CI; i++) {
            q[i] = fmaf(swq[i * CC + c], xv, q[i]);
            k[i] = fmaf(swk[i * CC + c], xv, k[i]);
            v[i] = fmaf(swv[i * CC + c], xv, v[i]);
        }
    }
#pragma unroll
    for (int i = 0; i < CI; i++) {
        q[i] += __shfl_xor_sync(0xffffffffu, q[i], 8);
        k[i] += __shfl_xor_sync(0xffffffffu, k[i], 8);
        v[i] += __shfl_xor_sync(0xffffffffu, v[i], 8);
        q[i] += __shfl_xor_sync(0xffffffffu, q[i], 16);
        k[i] += __shfl_xor_sync(0xffffffffu, k[i], 16);
        v[i] += __shfl_xor_sync(0xffffffffu, v[i], 16);
    }
    if (quarter == 0) {
        const float KS = 0.51006971f;  // log2(e)/sqrt(8)
        size_t base = ((size_t)b * NN + n) * CI;
        __half2 qh[4], kh[4];
#pragma unroll
        for (int i = 0; i < 4; i++) {
            qh[i] = __floats2half2_rn(q[2 * i], q[2 * i + 1]);
            kh[i] = __floats2half2_rn(k[2 * i] * KS, k[2 * i + 1] * KS);
        }
        *reinterpret_cast<uint4*>(&g_qh[base]) = *reinterpret_cast<uint4*>(qh);
        *reinterpret_cast<uint4*>(&g_kh[base]) = *reinterpret_cast<uint4*>(kh);
#pragma unroll
        for (int i = 0; i < CI; i++) sv[i][nloc] = __float2half_rn(v[i]);
    }
    __syncthreads();
    if (tid < 64) {
        int row = tid >> 3, chunk = tid & 7;
        int nbase = (blockIdx.x & 63) * 64;
        int bb = blockIdx.x >> 6;
        *reinterpret_cast<uint4*>(g_vt + ((size_t)bb * CI + row) * NN + nbase + chunk * 8) =
            *reinterpret_cast<const uint4*>(&sv[row][chunk * 8]);
    }
}

// ---------------- kernel 2: FA2 attention, m32/warp + split-K(8) -----------
// grid 2048: b = bx>>8, mt = (bx>>3)&31 (128 m rows), s8 = bx&7 (512 n each).
// 128 threads = 4 warps; warp w owns m rows [m0+32w, m0+32w+32) as two 16-row
// MMA tiles A (rows +0..15) and B (rows +16..31) sharing all Q/V fragments.
#define VPAD 264

__global__ void __launch_bounds__(128, 7) attn_kernel(const float* __restrict__ x,
                                                      const float* __restrict__ Wout,
                                                      float* __restrict__ out) {
    __shared__ __align__(16) uint4 sQ[256];          // Q tile [256][8] halves
    __shared__ __align__(16) __half sV[CI * VPAD];   // Vt tile [8][256] padded
    __shared__ float sAtt[128 * 9];
    __shared__ float sW[CC * CI];
    __shared__ int s_old;

    int tid = threadIdx.x, wid = tid >> 5, lane = tid & 31;
    int gid = lane >> 2, cp = lane & 3;
    int b = blockIdx.x >> 8, mt = (blockIdx.x >> 3) & 31, s8 = blockIdx.x & 7;
    int m0 = mt * 128;
    int nbase = s8 * 512;

    int mrowA = m0 + wid * 32 + gid;     // tile A rows: mrowA, mrowA+8
    int mrowB = mrowA + 16;              // tile B rows: mrowB, mrowB+8
    uint32_t kA0 = *reinterpret_cast<const uint32_t*>(
        &g_kh[((size_t)b * NN + mrowA) * CI + 2 * cp]);
    uint32_t kA1 = *reinterpret_cast<const uint32_t*>(
        &g_kh[((size_t)b * NN + mrowA + 8) * CI + 2 * cp]);
    uint32_t kB0 = *reinterpret_cast<const uint32_t*>(
        &g_kh[((size_t)b * NN + mrowB) * CI + 2 * cp]);
    uint32_t kB1 = *reinterpret_cast<const uint32_t*>(
        &g_kh[((size_t)b * NN + mrowB + 8) * CI + 2 * cp]);

    const uint4* qbase = reinterpret_cast<const uint4*>(g_qh + (size_t)b * NN * CI);
    const __half* vbase = g_vt + (size_t)b * CI * NN;

    // per-tile f16 PV accumulators, even/odd chunk streams
    uint32_t aAE0 = 0, aAE1 = 0, aAO0 = 0, aAO1 = 0;
    uint32_t aBE0 = 0, aBE1 = 0, aBO0 = 0, aBO1 = 0;
    // running f16x2 denominator accumulators (per tile, per row)
    uint32_t runA0 = 0, runA1 = 0, runB0 = 0, runB1 = 0;

    int r0 = tid >> 5, c0i = tid & 31;
    int r1 = (tid + 128) >> 5;

    uint4 q4a = qbase[nbase + tid];
    uint4 q4b = qbase[nbase + tid + 128];
    uint4 v4a = *reinterpret_cast<const uint4*>(vbase + (size_t)r0 * NN + nbase + c0i * 8);
    uint4 v4b = *reinterpret_cast<const uint4*>(vbase + (size_t)r1 * NN + nbase + c0i * 8);

    const uint32_t* sQw = reinterpret_cast<const uint32_t*>(sQ);
    const uint32_t* qp = sQw + gid * 4 + cp;
    const __half* vp = sV + gid * VPAD + 2 * cp;

    for (int bi = 0; bi < 2; bi++) {
        sQ[tid] = q4a;
        sQ[tid + 128] = q4b;
        *reinterpret_cast<uint4*>(&sV[r0 * VPAD + c0i * 8]) = v4a;
        *reinterpret_cast<uint4*>(&sV[r1 * VPAD + c0i * 8]) = v4b;
        __syncthreads();

        if (bi < 1) {
            int n1 = nbase + 256;
            q4a = qbase[n1 + tid];
            q4b = qbase[n1 + tid + 128];
            v4a = *reinterpret_cast<const uint4*>(vbase + (size_t)r0 * NN + n1 + c0i * 8);
            v4b = *reinterpret_cast<const uint4*>(vbase + (size_t)r1 * NN + n1 + c0i * 8);
        }

#pragma unroll
        for (int g = 0; g < 4; g++) {
#pragma unroll
            for (int c = 0; c < 4; c++) {
                int nc = g * 64 + c * 16;
                uint32_t qL = qp[nc * 4];
                uint32_t qH = qp[(nc + 8) * 4];

                uint32_t sA0, sA1, sA2, sA3, sB0, sB1, sB2, sB3;
                mma_s_f16(sA0, sA1, kA0, kA1, qL);
                mma_s_f16(sA2, sA3, kA0, kA1, qH);
                mma_s_f16(sB0, sB1, kB0, kB1, qL);
                mma_s_f16(sB2, sB3, kB0, kB1, qH);

                // hybrid exp: tile A odd chunks + tile B chunk 1 -> poly (f=3/8)
                uint32_t pA0, pA1, pA2, pA3, pB0, pB1, pB2, pB3;
                if (c & 1) {
                    pA0 = exp2_poly3(sA0); pA1 = exp2_poly3(sA1);
                    pA2 = exp2_poly3(sA2); pA3 = exp2_poly3(sA3);
                } else {
                    pA0 = ex2_h2(sA0); pA1 = ex2_h2(sA1);
                    pA2 = ex2_h2(sA2); pA3 = ex2_h2(sA3);
                }
                if (c == 1) {
                    pB0 = exp2_poly3(sB0); pB1 = exp2_poly3(sB1);
                    pB2 = exp2_poly3(sB2); pB3 = exp2_poly3(sB3);
                } else {
                    pB0 = ex2_h2(sB0); pB1 = ex2_h2(sB1);
                    pB2 = ex2_h2(sB2); pB3 = ex2_h2(sB3);
                }

                uint32_t vb0 = *reinterpret_cast<const uint32_t*>(vp + nc);
                uint32_t vb1 = *reinterpret_cast<const uint32_t*>(vp + nc + 8);

                if (c & 1) {
                    mma_pv_f16(aAO0, aAO1, pA0, pA1, pA2, pA3, vb0, vb1);
                    mma_pv_f16(aBO0, aBO1, pB0, pB1, pB2, pB3, vb0, vb1);
                } else {
                    mma_pv_f16(aAE0, aAE1, pA0, pA1, pA2, pA3, vb0, vb1);
                    mma_pv_f16(aBE0, aBE1, pB0, pB1, pB2, pB3, vb0, vb1);
                }

                // running denominators (f16x2): row r sums its P elements
                runA0 = hadd2u(runA0, hadd2u(pA0, pA2));
                runA1 = hadd2u(runA1, hadd2u(pA1, pA3));
                runB0 = hadd2u(runB0, hadd2u(pB0, pB2));
                runB1 = hadd2u(runB1, hadd2u(pB1, pB3));
            }
        }
        __syncthreads();
    }

    // finalize denominators: quad-reduce (cp dimension) in f32
    float2 fA0 = h2f2(runA0), fA1 = h2f2(runA1);
    float2 fB0 = h2f2(runB0), fB1 = h2f2(runB1);
    float dA0 = fA0.x + fA0.y, dA1 = fA1.x + fA1.y;
    float dB0 = fB0.x + fB0.y, dB1 = fB1.x + fB1.y;
    dA0 += __shfl_xor_sync(0xffffffffu, dA0, 1);
    dA0 += __shfl_xor_sync(0xffffffffu, dA0, 2);
    dA1 += __shfl_xor_sync(0xffffffffu, dA1, 1);
    dA1 += __shfl_xor_sync(0xffffffffu, dA1, 2);
    dB0 += __shfl_xor_sync(0xffffffffu, dB0, 1);
    dB0 += __shfl_xor_sync(0xffffffffu, dB0, 2);
    dB1 += __shfl_xor_sync(0xffffffffu, dB1, 1);
    dB1 += __shfl_xor_sync(0xffffffffu, dB1, 2);

    // combine E/O accumulators in f32 and store partials
    {
        size_t rb = ((size_t)s8 * BB + b) * NN;
        float2 e, o;
        e = h2f2(aAE0); o = h2f2(aAO0);
        *reinterpret_cast<float2*>(&g_pA[(rb + mrowA) * CI + 2 * cp]) =
            make_float2(e.x + o.x, e.y + o.y);
        e = h2f2(aAE1); o = h2f2(aAO1);
        *reinterpret_cast<float2*>(&g_pA[(rb + mrowA + 8) * CI + 2 * cp]) =
            make_float2(e.x + o.x, e.y + o.y);
        e = h2f2(aBE0); o = h2f2(aBO0);
        *reinterpret_cast<float2*>(&g_pA[(rb + mrowB) * CI + 2 * cp]) =
            make_float2(e.x + o.x, e.y + o.y);
        e = h2f2(aBE1); o = h2f2(aBO1);
        *reinterpret_cast<float2*>(&g_pA[(rb + mrowB + 8) * CI + 2 * cp]) =
            make_float2(e.x + o.x, e.y + o.y);
        if (cp == 0) {
            g_pD[rb + mrowA] = dA0;
            g_pD[rb + mrowA + 8] = dA1;
            g_pD[rb + mrowB] = dB0;
            g_pD[rb + mrowB + 8] = dB1;
        }
    }
    __threadfence();
    __syncthreads();
    if (tid == 0) s_old = atomicAdd(&g_cnt[b * 32 + mt], 1);
    __syncthreads();
    if (s_old != SPLITK - 1) return;       // last-arriving CTA merges + epilogue
    if (tid == 0) g_cnt[b * 32 + mt] = 0;  // reset for next (graph-replayed) launch
    __threadfence();

    for (int i = tid; i < CC * CI; i += 128) sW[i] = Wout[i];
    {
        int m = m0 + tid;                  // 128 threads, 1 m-row each
        float acc[CI] = {0, 0, 0, 0, 0, 0, 0, 0};
        float den = 0.f;
#pragma unroll
        for (int qq = 0; qq < SPLITK; qq++) {
            size_t rb = ((size_t)qq * BB + b) * NN + m;
            const float4* a = reinterpret_cast<const float4*>(&g_pA[rb * CI]);
            float4 x0 = a[0], x1 = a[1];
            acc[0] += x0.x; acc[1] += x0.y; acc[2] += x0.z; acc[3] += x0.w;
            acc[4] += x1.x; acc[5] += x1.y; acc[6] += x1.z; acc[7] += x1.w;
            den += g_pD[rb];
        }
        float inv = 1.0f / den;
#pragma unroll
        for (int i = 0; i < CI; i++) sAtt[tid * 9 + i] = acc[i] * inv;
    }
    __syncthreads();

    // epilogue: out = x + 0.1 * Wout @ att  (1 m-row per thread, 64 channels)
    float att[CI];
#pragma unroll
    for (int i = 0; i < CI; i++) att[i] = sAtt[tid * 9 + i];

    int m = m0 + tid;
    const float* xp = x + (size_t)b * CC * NN + m;
    float* op = out + (size_t)b * CC * NN + m;
#pragma unroll 8
    for (int c = 0; c < CC; c++) {
        float o = 0.f;
#pragma unroll
        for (int i = 0; i < CI; i++) o = fmaf(sW[c * CI + i], att[i], o);
        op[(size_t)c * NN] = fmaf(0.1f, o, xp[(size_t)c * NN]);
    }
}

// ---------------- launch ----------------
extern "C" void kernel_launch(void* const* d_in, const int* in_sizes, int n_in,
                              void* d_out, int out_size) {
    const float* x = (const float*)d_in[0];
    const float* Wq = (const float*)d_in[1];
    const float* Wk = (const float*)d_in[2];
    const float* Wv = (const float*)d_in[3];
    const float* Wout = (const float*)d_in[4];
    float* out = (float*)d_out;

    proj_kernel<<<512, 256>>>(x, Wq, Wk, Wv);
    attn_kernel<<<2048, 128>>>(x, Wout, out);
}